// round 9
// baseline (speedup 1.0000x reference)
#include <cuda_runtime.h>
#include <cuda_bf16.h>
#include <cuda_fp16.h>
#include <cstdint>

#define MAXN 50000
#define MAXE 800000
#define MAXEE (MAXN + MAXE)
#define F 128
#define NHEAD 2
#define NEG 0.2f
#define SCANB 256
#define TM 128

// ---------------- scratch (device globals; no allocation) ----------------
__device__ __half g_hh[(size_t)MAXN * F];   // h in fp16 (gather path)
__device__ float g_feat[(size_t)MAXN * F];
__device__ float g_als[MAXN * NHEAD];
__device__ float g_ald[MAXN * NHEAD];
__device__ int g_rank[MAXEE];               // edge rank within its dst segment
__device__ int g_cnt[MAXN];
__device__ int g_incl[MAXN];
__device__ int g_bsum[(MAXN + SCANB - 1) / SCANB];
__device__ int g_rowptr[MAXN + 1];
__device__ int g_esrc[MAXEE];
__device__ __nv_bfloat16 g_wth[3][F * F];   // W^T hi, [n][k]
__device__ __nv_bfloat16 g_wtl[3][F * F];   // W^T lo, [n][k]

__device__ __forceinline__ float leaky(float x) { return x > 0.f ? x : NEG * x; }

__device__ __forceinline__ uint32_t smem_u32(const void* p) {
    uint32_t a;
    asm("{ .reg .u64 t; cvta.to.shared.u64 t, %1; cvt.u32.u64 %0, t; }" : "=r"(a) : "l"(p));
    return a;
}

// ---------------- graph build ----------------
__global__ void k_build_hist(const int* __restrict__ ei, int E, int N) {
    int base = (blockIdx.x * blockDim.x + threadIdx.x) * 4;
    int EE = E + N;
    if (base >= EE) return;
    if (base + 3 < E) {
        int4 d = *(const int4*)(ei + E + base);
        int4 r;
        r.x = atomicAdd(&g_cnt[d.x], 1);
        r.y = atomicAdd(&g_cnt[d.y], 1);
        r.z = atomicAdd(&g_cnt[d.z], 1);
        r.w = atomicAdd(&g_cnt[d.w], 1);
        *(int4*)(g_rank + base) = r;
    } else {
#pragma unroll
        for (int q = 0; q < 4; q++) {
            int i = base + q;
            if (i >= EE) break;
            int d = (i < E) ? ei[E + i] : (i - E);
            g_rank[i] = atomicAdd(&g_cnt[d], 1);
        }
    }
}
__global__ void k_scan1(int N) {
    __shared__ int sm[SCANB];
    int i = blockIdx.x * SCANB + threadIdx.x;
    int v = (i < N) ? g_cnt[i] : 0;
    sm[threadIdx.x] = v;
    __syncthreads();
#pragma unroll
    for (int o = 1; o < SCANB; o <<= 1) {
        int t = (threadIdx.x >= o) ? sm[threadIdx.x - o] : 0;
        __syncthreads();
        sm[threadIdx.x] += t;
        __syncthreads();
    }
    if (i < N) g_incl[i] = sm[threadIdx.x];
    if (threadIdx.x == SCANB - 1) g_bsum[blockIdx.x] = sm[SCANB - 1];
}
__global__ void k_scan23(int N, int EE, int nb) {
    __shared__ int sm[SCANB];
    int v = (threadIdx.x < nb) ? g_bsum[threadIdx.x] : 0;
    sm[threadIdx.x] = v;
    __syncthreads();
#pragma unroll
    for (int o = 1; o < SCANB; o <<= 1) {
        int t = (threadIdx.x >= o) ? sm[threadIdx.x - o] : 0;
        __syncthreads();
        sm[threadIdx.x] += t;
        __syncthreads();
    }
    int bid = blockIdx.x;
    int boff = sm[bid] - g_bsum[bid];
    int i = bid * SCANB + threadIdx.x;
    if (i < N) g_rowptr[i] = g_incl[i] - g_cnt[i] + boff;
    if (i == 0) g_rowptr[N] = EE;
}
__global__ void k_fill(const int* __restrict__ ei, int E, int N) {
    int base = (blockIdx.x * blockDim.x + threadIdx.x) * 4;
    int EE = E + N;
    if (base >= EE) return;
    if (base + 3 < E) {
        int4 s = *(const int4*)(ei + base);
        int4 d = *(const int4*)(ei + E + base);
        int4 r = *(const int4*)(g_rank + base);
        g_esrc[g_rowptr[d.x] + r.x] = s.x;
        g_esrc[g_rowptr[d.y] + r.y] = s.y;
        g_esrc[g_rowptr[d.z] + r.z] = s.z;
        g_esrc[g_rowptr[d.w] + r.w] = s.w;
    } else {
#pragma unroll
        for (int q = 0; q < 4; q++) {
            int i = base + q;
            if (i >= EE) break;
            int s, d;
            if (i < E) { s = ei[i]; d = ei[E + i]; }
            else       { s = i - E; d = i - E; }
            g_esrc[g_rowptr[d] + g_rank[i]] = s;
        }
    }
}

// ---------------- W prep ----------------
__global__ void k_prep_w3(const float* __restrict__ W0, const float* __restrict__ W1,
                          const float* __restrict__ W2) {
    int i = blockIdx.x * blockDim.x + threadIdx.x;
    if (i >= 3 * F * F) return;
    int l = i / (F * F), j = i % (F * F);
    const float* W = (l == 0) ? W0 : ((l == 1) ? W1 : W2);
    int k = j / F, n = j % F;
    float v = W[j];
    __nv_bfloat16 h = __float2bfloat16_rn(v);
    float r = v - __bfloat162float(h);
    g_wth[l][n * F + k] = h;
    g_wtl[l][n * F + k] = __float2bfloat16_rn(r);
}

// ---------------- mma.sync GEMM + fused attention logits ----------------
#define TSTRIDE 136
#define TROWB (TSTRIDE * 2)
#define TILE_BYTES (128 * TROWB)
#define OFF_AS 0
#define OFF_AD 512
#define OFF_XHI 1024
#define OFF_XLO (OFF_XHI + TILE_BYTES)
#define OFF_WHI (OFF_XLO + TILE_BYTES)
#define OFF_WLO (OFF_WHI + TILE_BYTES)
#define GEMM_SMEM_TOTAL (OFF_WLO + TILE_BYTES)

__device__ __forceinline__ void ldsm4(uint32_t addr, uint32_t& r0, uint32_t& r1,
                                      uint32_t& r2, uint32_t& r3) {
    asm volatile("ldmatrix.sync.aligned.m8n8.x4.shared.b16 {%0,%1,%2,%3}, [%4];"
                 : "=r"(r0), "=r"(r1), "=r"(r2), "=r"(r3) : "r"(addr));
}
__device__ __forceinline__ void mma16816(float* c, const uint32_t* a, uint32_t b0, uint32_t b1) {
    asm volatile(
        "mma.sync.aligned.m16n8k16.row.col.f32.bf16.bf16.f32 "
        "{%0,%1,%2,%3}, {%4,%5,%6,%7}, {%8,%9}, {%0,%1,%2,%3};"
        : "+f"(c[0]), "+f"(c[1]), "+f"(c[2]), "+f"(c[3])
        : "r"(a[0]), "r"(a[1]), "r"(a[2]), "r"(a[3]), "r"(b0), "r"(b1));
}
__device__ __forceinline__ uint32_t pack_bf16x2(float a, float b) {
    __nv_bfloat16 ha = __float2bfloat16_rn(a), hb = __float2bfloat16_rn(b);
    return (uint32_t)__bfloat16_as_ushort(ha) | ((uint32_t)__bfloat16_as_ushort(hb) << 16);
}

__global__ void __launch_bounds__(256, 1)
k_gemm_tc(const float* __restrict__ A, const __nv_bfloat16* __restrict__ wth,
          const __nv_bfloat16* __restrict__ wtl, const float* __restrict__ a_src,
          const float* __restrict__ a_dst, int N) {
    extern __shared__ char smem[];
    uint32_t sb = smem_u32(smem);
    int tid = threadIdx.x;
    int wid = tid >> 5, lane = tid & 31;
    int row0 = blockIdx.x * TM;

    if (tid < F) {
        *(float*)(smem + OFF_AS + tid * 4) = __ldg(a_src + tid);
        *(float*)(smem + OFF_AD + tid * 4) = __ldg(a_dst + tid);
    }

    const float4* A4 = (const float4*)A;
#pragma unroll
    for (int it = 0; it < 16; it++) {
        int i = tid + it * 256;
        int r = i >> 5, c4 = (i & 31) << 2;
        int gr = row0 + r;
        float4 v = (gr < N) ? A4[(size_t)gr * 32 + (i & 31)] : make_float4(0.f, 0.f, 0.f, 0.f);
        uint2 hi, lo;
        hi.x = pack_bf16x2(v.x, v.y);
        hi.y = pack_bf16x2(v.z, v.w);
        float rx = v.x - __bfloat162float(__float2bfloat16_rn(v.x));
        float ry = v.y - __bfloat162float(__float2bfloat16_rn(v.y));
        float rz = v.z - __bfloat162float(__float2bfloat16_rn(v.z));
        float rw = v.w - __bfloat162float(__float2bfloat16_rn(v.w));
        lo.x = pack_bf16x2(rx, ry);
        lo.y = pack_bf16x2(rz, rw);
        uint32_t off = (uint32_t)(r * TROWB + c4 * 2);
        *(uint2*)(smem + OFF_XHI + off) = hi;
        *(uint2*)(smem + OFF_XLO + off) = lo;
    }
    const uint2* WH2 = (const uint2*)wth;
    const uint2* WL2 = (const uint2*)wtl;
#pragma unroll
    for (int it = 0; it < 16; it++) {
        int i = tid + it * 256;
        int r = i >> 5, c4 = (i & 31) << 2;
        uint32_t off = (uint32_t)(r * TROWB + c4 * 2);
        *(uint2*)(smem + OFF_WHI + off) = WH2[i];
        *(uint2*)(smem + OFF_WLO + off) = WL2[i];
    }
    __syncthreads();

    int warp_m = wid & 3;
    int warp_n = wid >> 2;       // == head
    int m0 = warp_m * 32;
    int n0 = warp_n * 64;

    float acc[2][8][4];
#pragma unroll
    for (int mt = 0; mt < 2; mt++)
#pragma unroll
        for (int nt = 0; nt < 8; nt++)
#pragma unroll
            for (int q = 0; q < 4; q++) acc[mt][nt][q] = 0.f;

    int a_row_in = (lane & 7) + ((lane >> 3) & 1) * 8;
    int a_koff = (lane >> 4) * 16;
    int b_row_in = (lane & 7) + ((lane >> 4) & 1) * 8;
    int b_koff = ((lane >> 3) & 1) * 16;

#pragma unroll
    for (int t = 0; t < 3; t++) {
        uint32_t abase = sb + ((t == 2) ? OFF_XLO : OFF_XHI);
        uint32_t bbase = sb + ((t == 1) ? OFF_WLO : OFF_WHI);
#pragma unroll
        for (int ks = 0; ks < 8; ks++) {
            int kb = ks * 32;
            uint32_t afr[2][4];
#pragma unroll
            for (int mt = 0; mt < 2; mt++) {
                uint32_t ad = abase + (uint32_t)((m0 + mt * 16 + a_row_in) * TROWB + kb + a_koff);
                ldsm4(ad, afr[mt][0], afr[mt][1], afr[mt][2], afr[mt][3]);
            }
            uint32_t bfr[4][4];
#pragma unroll
            for (int pt = 0; pt < 4; pt++) {
                uint32_t bd = bbase + (uint32_t)((n0 + pt * 16 + b_row_in) * TROWB + kb + b_koff);
                ldsm4(bd, bfr[pt][0], bfr[pt][1], bfr[pt][2], bfr[pt][3]);
            }
#pragma unroll
            for (int mt = 0; mt < 2; mt++)
#pragma unroll
                for (int nt = 0; nt < 8; nt++)
                    mma16816(acc[mt][nt], afr[mt], bfr[nt >> 1][(nt & 1) * 2],
                             bfr[nt >> 1][(nt & 1) * 2 + 1]);
        }
    }

    const float* sAS = (const float*)(smem + OFF_AS);
    const float* sAD = (const float*)(smem + OFF_AD);
    float ss[2][2] = {{0.f, 0.f}, {0.f, 0.f}};
    float dd[2][2] = {{0.f, 0.f}, {0.f, 0.f}};
#pragma unroll
    for (int nt = 0; nt < 8; nt++) {
        int col = n0 + nt * 8 + ((lane & 3) << 1);
        float as0 = sAS[col], as1 = sAS[col + 1];
        float ad0 = sAD[col], ad1 = sAD[col + 1];
#pragma unroll
        for (int mt = 0; mt < 2; mt++) {
            float c0 = acc[mt][nt][0], c1 = acc[mt][nt][1];
            float c2 = acc[mt][nt][2], c3 = acc[mt][nt][3];
            int r0 = row0 + m0 + mt * 16 + (lane >> 2);
            if (r0 < N) *(__half2*)(g_hh + (size_t)r0 * F + col) = __floats2half2_rn(c0, c1);
            if (r0 + 8 < N)
                *(__half2*)(g_hh + (size_t)(r0 + 8) * F + col) = __floats2half2_rn(c2, c3);
            ss[mt][0] += c0 * as0 + c1 * as1;
            ss[mt][1] += c2 * as0 + c3 * as1;
            dd[mt][0] += c0 * ad0 + c1 * ad1;
            dd[mt][1] += c2 * ad0 + c3 * ad1;
        }
    }
#pragma unroll
    for (int mt = 0; mt < 2; mt++)
#pragma unroll
        for (int rh = 0; rh < 2; rh++) {
            ss[mt][rh] += __shfl_xor_sync(0xffffffffu, ss[mt][rh], 1);
            ss[mt][rh] += __shfl_xor_sync(0xffffffffu, ss[mt][rh], 2);
            dd[mt][rh] += __shfl_xor_sync(0xffffffffu, dd[mt][rh], 1);
            dd[mt][rh] += __shfl_xor_sync(0xffffffffu, dd[mt][rh], 2);
        }
    if ((lane & 3) == 0) {
#pragma unroll
        for (int mt = 0; mt < 2; mt++)
#pragma unroll
            for (int rh = 0; rh < 2; rh++) {
                int m = row0 + m0 + mt * 16 + rh * 8 + (lane >> 2);
                if (m < N) {
                    g_als[m * NHEAD + warp_n] = ss[mt][rh];
                    g_ald[m * NHEAD + warp_n] = dd[mt][rh];
                }
            }
    }
}

// ---------------- fused CSR aggregation: half-warp per edge, 16B loads ---------
// lane = 16*half + li. Lane covers feats 8li..8li+7 (one uint4 of the fp16 row).
// half 0 takes edges beg, beg+2, ...; half 1 takes beg+1, beg+3, ...
// Final shfl_xor(16) merges the two disjoint edge sets.
__global__ void k_aggregate(const float* __restrict__ bias, int residual, int fuse_lin,
                            const float* __restrict__ lin_w, const float* __restrict__ lin_b,
                            float* __restrict__ out, int N) {
    int d = (blockIdx.x * blockDim.x + threadIdx.x) >> 5;
    if (d >= N) return;
    int lane = threadIdx.x & 31;
    int half = lane >> 4, li = lane & 15;
    int head = li >> 3;

    float ald = g_ald[d * NHEAD + head];
    int beg = g_rowptr[d], end = g_rowptr[d + 1];

    float acc[8];
#pragma unroll
    for (int q = 0; q < 8; q++) acc[q] = 0.f;
    float sum = 0.f;
    const uint4* H4 = (const uint4*)g_hh;   // 16 uint4 per row

    int j = beg + half;
    // unroll 2: two edges in flight per half-warp (4 per warp)
    for (; j + 2 < end; j += 4) {
        int s0 = g_esrc[j], s1 = g_esrc[j + 2];
        float e0 = __expf(leaky(g_als[s0 * NHEAD + head] + ald));
        float e1 = __expf(leaky(g_als[s1 * NHEAD + head] + ald));
        uint4 r0 = __ldg(H4 + (size_t)s0 * 16 + li);
        uint4 r1 = __ldg(H4 + (size_t)s1 * 16 + li);
        sum += e0 + e1;
        float2 f0 = __half22float2(*(__half2*)&r0.x), f1 = __half22float2(*(__half2*)&r0.y);
        float2 f2 = __half22float2(*(__half2*)&r0.z), f3 = __half22float2(*(__half2*)&r0.w);
        float2 g0 = __half22float2(*(__half2*)&r1.x), g1 = __half22float2(*(__half2*)&r1.y);
        float2 g2 = __half22float2(*(__half2*)&r1.z), g3 = __half22float2(*(__half2*)&r1.w);
        acc[0] += e0 * f0.x + e1 * g0.x; acc[1] += e0 * f0.y + e1 * g0.y;
        acc[2] += e0 * f1.x + e1 * g1.x; acc[3] += e0 * f1.y + e1 * g1.y;
        acc[4] += e0 * f2.x + e1 * g2.x; acc[5] += e0 * f2.y + e1 * g2.y;
        acc[6] += e0 * f3.x + e1 * g3.x; acc[7] += e0 * f3.y + e1 * g3.y;
    }
    for (; j < end; j += 2) {
        int s = g_esrc[j];
        float ex = __expf(leaky(g_als[s * NHEAD + head] + ald));
        uint4 r = __ldg(H4 + (size_t)s * 16 + li);
        sum += ex;
        float2 f0 = __half22float2(*(__half2*)&r.x), f1 = __half22float2(*(__half2*)&r.y);
        float2 f2 = __half22float2(*(__half2*)&r.z), f3 = __half22float2(*(__half2*)&r.w);
        acc[0] += ex * f0.x; acc[1] += ex * f0.y;
        acc[2] += ex * f1.x; acc[3] += ex * f1.y;
        acc[4] += ex * f2.x; acc[5] += ex * f2.y;
        acc[6] += ex * f3.x; acc[7] += ex * f3.y;
    }

    // merge halves (disjoint edge sets)
#pragma unroll
    for (int q = 0; q < 8; q++) acc[q] += __shfl_xor_sync(0xffffffffu, acc[q], 16);
    sum += __shfl_xor_sync(0xffffffffu, sum, 16);

    float inv = 1.f / sum;
    const float4* B4 = (const float4*)bias;
    float4 b0 = __ldg(B4 + 2 * li), b1 = __ldg(B4 + 2 * li + 1);
    float v[8];
    v[0] = acc[0] * inv + b0.x; v[1] = acc[1] * inv + b0.y;
    v[2] = acc[2] * inv + b0.z; v[3] = acc[3] * inv + b0.w;
    v[4] = acc[4] * inv + b1.x; v[5] = acc[5] * inv + b1.y;
    v[6] = acc[6] * inv + b1.z; v[7] = acc[7] * inv + b1.w;
    if (residual) {
        const float4* FP = (const float4*)g_feat + (size_t)d * 32 + 2 * li;
        float4 f0 = FP[0], f1 = FP[1];
        v[0] += f0.x; v[1] += f0.y; v[2] += f0.z; v[3] += f0.w;
        v[4] += f1.x; v[5] += f1.y; v[6] += f1.z; v[7] += f1.w;
    }
#pragma unroll
    for (int q = 0; q < 8; q++) v[q] = leaky(v[q]);

    if (!fuse_lin) {
        if (half == 0) {
            float4* FP = (float4*)g_feat + (size_t)d * 32 + 2 * li;
            FP[0] = make_float4(v[0], v[1], v[2], v[3]);
            FP[1] = make_float4(v[4], v[5], v[6], v[7]);
        }
    } else {
        const float4* LW = (const float4*)lin_w;
        float4 w0 = __ldg(LW + 2 * li), w1 = __ldg(LW + 2 * li + 1);
        float s = v[0] * w0.x + v[1] * w0.y + v[2] * w0.z + v[3] * w0.w +
                  v[4] * w1.x + v[5] * w1.y + v[6] * w1.z + v[7] * w1.w;
#pragma unroll
        for (int o = 8; o; o >>= 1) s += __shfl_xor_sync(0xffffffffu, s, o);
        if (lane == 0) out[d] = s + __ldg(lin_b);
    }
}

// ---------------- host ----------------
extern "C" void kernel_launch(void* const* d_in, const int* in_sizes, int n_in,
                              void* d_out, int out_size) {
    const float* x = (const float*)d_in[0];
    const int* ei = (const int*)d_in[1];
    const float* W[3] = {(const float*)d_in[2], (const float*)d_in[6], (const float*)d_in[10]};
    const float* as[3] = {(const float*)d_in[3], (const float*)d_in[7], (const float*)d_in[11]};
    const float* ad[3] = {(const float*)d_in[4], (const float*)d_in[8], (const float*)d_in[12]};
    const float* bs[3] = {(const float*)d_in[5], (const float*)d_in[9], (const float*)d_in[13]};
    const float* lin_w = (const float*)d_in[14];
    const float* lin_b = (const float*)d_in[15];

    int N = in_sizes[0] / F;
    int E = in_sizes[1] / 2;
    int EE = E + N;
    int nb = (N + SCANB - 1) / SCANB;

    static bool init_done = false;
    static cudaStream_t s2;
    static cudaEvent_t ev_fork, ev_gemm1;
    if (!init_done) {
        cudaFuncSetAttribute(k_gemm_tc, cudaFuncAttributeMaxDynamicSharedMemorySize,
                             GEMM_SMEM_TOTAL);
        cudaStreamCreateWithFlags(&s2, cudaStreamNonBlocking);
        cudaEventCreateWithFlags(&ev_fork, cudaEventDisableTiming);
        cudaEventCreateWithFlags(&ev_gemm1, cudaEventDisableTiming);
        init_done = true;
    }

    float* feat_ptr = nullptr;
    cudaGetSymbolAddress((void**)&feat_ptr, g_feat);
    int* cnt_ptr = nullptr;
    cudaGetSymbolAddress((void**)&cnt_ptr, g_cnt);
    __nv_bfloat16* wth_ptr = nullptr;
    cudaGetSymbolAddress((void**)&wth_ptr, g_wth);
    __nv_bfloat16* wtl_ptr = nullptr;
    cudaGetSymbolAddress((void**)&wtl_ptr, g_wtl);

    const int TB = 256;
    int gemm_blocks = (N + TM - 1) / TM;
    int warpN_blocks = (N * 32 + TB - 1) / TB;
    int edge4_blocks = ((EE + 3) / 4 + TB - 1) / TB;
    int prep_blocks = (3 * F * F + TB - 1) / TB;

    // ---- fork: W prep + layer-1 GEMM on s2, CSR build on stream 0 ----
    cudaEventRecord(ev_fork, 0);
    cudaStreamWaitEvent(s2, ev_fork, 0);
    k_prep_w3<<<prep_blocks, TB, 0, s2>>>(W[0], W[1], W[2]);
    k_gemm_tc<<<gemm_blocks, 256, GEMM_SMEM_TOTAL, s2>>>(
        x, wth_ptr, wtl_ptr, as[0], ad[0], N);
    cudaEventRecord(ev_gemm1, s2);

    cudaMemsetAsync(cnt_ptr, 0, N * sizeof(int));
    k_build_hist<<<edge4_blocks, TB>>>(ei, E, N);
    k_scan1<<<nb, SCANB>>>(N);
    k_scan23<<<nb, SCANB>>>(N, EE, nb);
    k_fill<<<edge4_blocks, TB>>>(ei, E, N);

    // ---- join, then the rest on stream 0 ----
    cudaStreamWaitEvent(0, ev_gemm1, 0);
    k_aggregate<<<warpN_blocks, TB>>>(bs[0], 0, 0, lin_w, lin_b, (float*)d_out, N);

    for (int l = 1; l < 3; l++) {
        k_gemm_tc<<<gemm_blocks, 256, GEMM_SMEM_TOTAL>>>(
            feat_ptr, wth_ptr + (size_t)l * F * F, wtl_ptr + (size_t)l * F * F,
            as[l], ad[l], N);
        k_aggregate<<<warpN_blocks, TB>>>(bs[l], 1, l == 2, lin_w, lin_b,
                                          (float*)d_out, N);
    }
}

// round 10
// speedup vs baseline: 1.0314x; 1.0314x over previous
#include <cuda_runtime.h>
#include <cuda_bf16.h>
#include <cuda_fp16.h>
#include <cstdint>

#define MAXN 50000
#define MAXE 800000
#define MAXEE (MAXN + MAXE)
#define F 128
#define NHEAD 2
#define NEG 0.2f
#define SCANB 256
#define TM 128

// ---------------- scratch (device globals; no allocation) ----------------
__device__ __half g_hh[(size_t)MAXN * F];   // h in fp16 (gather path)
__device__ float g_feat[(size_t)MAXN * F];
__device__ float g_als[MAXN * NHEAD];
__device__ float g_ald[MAXN * NHEAD];
__device__ int g_rank[MAXEE];               // edge rank within its dst segment
__device__ int g_cnt[MAXN];
__device__ int g_incl[MAXN];
__device__ int g_bsum[(MAXN + SCANB - 1) / SCANB];
__device__ int g_rowptr[MAXN + 1];
__device__ int g_esrc[MAXEE];
__device__ __nv_bfloat16 g_wth[3][F * F];   // W^T hi, [n][k]
__device__ __nv_bfloat16 g_wtl[3][F * F];   // W^T lo, [n][k]

__device__ __forceinline__ float leaky(float x) { return x > 0.f ? x : NEG * x; }

__device__ __forceinline__ uint32_t smem_u32(const void* p) {
    uint32_t a;
    asm("{ .reg .u64 t; cvta.to.shared.u64 t, %1; cvt.u32.u64 %0, t; }" : "=r"(a) : "l"(p));
    return a;
}

// ---------------- graph build ----------------
__global__ void k_build_hist(const int* __restrict__ ei, int E, int N) {
    int base = (blockIdx.x * blockDim.x + threadIdx.x) * 4;
    int EE = E + N;
    if (base >= EE) return;
    if (base + 3 < E) {
        int4 d = *(const int4*)(ei + E + base);
        int4 r;
        r.x = atomicAdd(&g_cnt[d.x], 1);
        r.y = atomicAdd(&g_cnt[d.y], 1);
        r.z = atomicAdd(&g_cnt[d.z], 1);
        r.w = atomicAdd(&g_cnt[d.w], 1);
        *(int4*)(g_rank + base) = r;
    } else {
#pragma unroll
        for (int q = 0; q < 4; q++) {
            int i = base + q;
            if (i >= EE) break;
            int d = (i < E) ? ei[E + i] : (i - E);
            g_rank[i] = atomicAdd(&g_cnt[d], 1);
        }
    }
}
// 256-thread block inclusive scan via warp shuffles (2 syncs, no log-step smem).
__global__ void k_scan1(int N) {
    __shared__ int wsum[8];
    int i = blockIdx.x * SCANB + threadIdx.x;
    int lane = threadIdx.x & 31, w = threadIdx.x >> 5;
    int x = (i < N) ? g_cnt[i] : 0;
#pragma unroll
    for (int o = 1; o < 32; o <<= 1) {
        int t = __shfl_up_sync(0xffffffffu, x, o);
        if (lane >= o) x += t;
    }
    if (lane == 31) wsum[w] = x;
    __syncthreads();
    if (w == 0 && lane < 8) {
        int y = wsum[lane];
#pragma unroll
        for (int o = 1; o < 8; o <<= 1) {
            int t = __shfl_up_sync(0xffu, y, o);
            if (lane >= o) y += t;
        }
        wsum[lane] = y;
    }
    __syncthreads();
    int incl = x + (w ? wsum[w - 1] : 0);
    if (i < N) g_incl[i] = incl;
    if (threadIdx.x == SCANB - 1) g_bsum[blockIdx.x] = incl;
}
// every block redundantly scans the <=256 block sums (shuffle), finishes rowptr.
__global__ void k_scan23(int N, int EE, int nb) {
    __shared__ int wsum[8];
    int lane = threadIdx.x & 31, w = threadIdx.x >> 5;
    int v = (threadIdx.x < nb) ? g_bsum[threadIdx.x] : 0;
    int x = v;
#pragma unroll
    for (int o = 1; o < 32; o <<= 1) {
        int t = __shfl_up_sync(0xffffffffu, x, o);
        if (lane >= o) x += t;
    }
    if (lane == 31) wsum[w] = x;
    __syncthreads();
    if (w == 0 && lane < 8) {
        int y = wsum[lane];
#pragma unroll
        for (int o = 1; o < 8; o <<= 1) {
            int t = __shfl_up_sync(0xffu, y, o);
            if (lane >= o) y += t;
        }
        wsum[lane] = y;
    }
    __syncthreads();
    __shared__ int excl_s[SCANB];
    excl_s[threadIdx.x] = x + (w ? wsum[w - 1] : 0) - v;  // exclusive block prefix
    __syncthreads();
    int bid = blockIdx.x;
    int boff = excl_s[bid];
    int i = bid * SCANB + threadIdx.x;
    if (i < N) g_rowptr[i] = g_incl[i] - g_cnt[i] + boff;
    if (i == 0) g_rowptr[N] = EE;
}
__global__ void k_fill(const int* __restrict__ ei, int E, int N) {
    int base = (blockIdx.x * blockDim.x + threadIdx.x) * 4;
    int EE = E + N;
    if (base >= EE) return;
    if (base + 3 < E) {
        int4 s = *(const int4*)(ei + base);
        int4 d = *(const int4*)(ei + E + base);
        int4 r = *(const int4*)(g_rank + base);
        g_esrc[g_rowptr[d.x] + r.x] = s.x;
        g_esrc[g_rowptr[d.y] + r.y] = s.y;
        g_esrc[g_rowptr[d.z] + r.z] = s.z;
        g_esrc[g_rowptr[d.w] + r.w] = s.w;
    } else {
#pragma unroll
        for (int q = 0; q < 4; q++) {
            int i = base + q;
            if (i >= EE) break;
            int s, d;
            if (i < E) { s = ei[i]; d = ei[E + i]; }
            else       { s = i - E; d = i - E; }
            g_esrc[g_rowptr[d] + g_rank[i]] = s;
        }
    }
}

// ---------------- W prep ----------------
__global__ void k_prep_w3(const float* __restrict__ W0, const float* __restrict__ W1,
                          const float* __restrict__ W2) {
    int i = blockIdx.x * blockDim.x + threadIdx.x;
    if (i >= 3 * F * F) return;
    int l = i / (F * F), j = i % (F * F);
    const float* W = (l == 0) ? W0 : ((l == 1) ? W1 : W2);
    int k = j / F, n = j % F;
    float v = W[j];
    __nv_bfloat16 h = __float2bfloat16_rn(v);
    float r = v - __bfloat162float(h);
    g_wth[l][n * F + k] = h;
    g_wtl[l][n * F + k] = __float2bfloat16_rn(r);
}

// ---------------- mma.sync GEMM + fused attention logits ----------------
#define TSTRIDE 136
#define TROWB (TSTRIDE * 2)
#define TILE_BYTES (128 * TROWB)
#define OFF_AS 0
#define OFF_AD 512
#define OFF_XHI 1024
#define OFF_XLO (OFF_XHI + TILE_BYTES)
#define OFF_WHI (OFF_XLO + TILE_BYTES)
#define OFF_WLO (OFF_WHI + TILE_BYTES)
#define GEMM_SMEM_TOTAL (OFF_WLO + TILE_BYTES)

__device__ __forceinline__ void ldsm4(uint32_t addr, uint32_t& r0, uint32_t& r1,
                                      uint32_t& r2, uint32_t& r3) {
    asm volatile("ldmatrix.sync.aligned.m8n8.x4.shared.b16 {%0,%1,%2,%3}, [%4];"
                 : "=r"(r0), "=r"(r1), "=r"(r2), "=r"(r3) : "r"(addr));
}
__device__ __forceinline__ void mma16816(float* c, const uint32_t* a, uint32_t b0, uint32_t b1) {
    asm volatile(
        "mma.sync.aligned.m16n8k16.row.col.f32.bf16.bf16.f32 "
        "{%0,%1,%2,%3}, {%4,%5,%6,%7}, {%8,%9}, {%0,%1,%2,%3};"
        : "+f"(c[0]), "+f"(c[1]), "+f"(c[2]), "+f"(c[3])
        : "r"(a[0]), "r"(a[1]), "r"(a[2]), "r"(a[3]), "r"(b0), "r"(b1));
}
__device__ __forceinline__ uint32_t pack_bf16x2(float a, float b) {
    __nv_bfloat16 ha = __float2bfloat16_rn(a), hb = __float2bfloat16_rn(b);
    return (uint32_t)__bfloat16_as_ushort(ha) | ((uint32_t)__bfloat16_as_ushort(hb) << 16);
}

__global__ void __launch_bounds__(256, 1)
k_gemm_tc(const float* __restrict__ A, const __nv_bfloat16* __restrict__ wth,
          const __nv_bfloat16* __restrict__ wtl, const float* __restrict__ a_src,
          const float* __restrict__ a_dst, int N) {
    extern __shared__ char smem[];
    uint32_t sb = smem_u32(smem);
    int tid = threadIdx.x;
    int wid = tid >> 5, lane = tid & 31;
    int row0 = blockIdx.x * TM;

    if (tid < F) {
        *(float*)(smem + OFF_AS + tid * 4) = __ldg(a_src + tid);
        *(float*)(smem + OFF_AD + tid * 4) = __ldg(a_dst + tid);
    }

    const float4* A4 = (const float4*)A;
#pragma unroll
    for (int it = 0; it < 16; it++) {
        int i = tid + it * 256;
        int r = i >> 5, c4 = (i & 31) << 2;
        int gr = row0 + r;
        float4 v = (gr < N) ? A4[(size_t)gr * 32 + (i & 31)] : make_float4(0.f, 0.f, 0.f, 0.f);
        uint2 hi, lo;
        hi.x = pack_bf16x2(v.x, v.y);
        hi.y = pack_bf16x2(v.z, v.w);
        float rx = v.x - __bfloat162float(__float2bfloat16_rn(v.x));
        float ry = v.y - __bfloat162float(__float2bfloat16_rn(v.y));
        float rz = v.z - __bfloat162float(__float2bfloat16_rn(v.z));
        float rw = v.w - __bfloat162float(__float2bfloat16_rn(v.w));
        lo.x = pack_bf16x2(rx, ry);
        lo.y = pack_bf16x2(rz, rw);
        uint32_t off = (uint32_t)(r * TROWB + c4 * 2);
        *(uint2*)(smem + OFF_XHI + off) = hi;
        *(uint2*)(smem + OFF_XLO + off) = lo;
    }
    const uint2* WH2 = (const uint2*)wth;
    const uint2* WL2 = (const uint2*)wtl;
#pragma unroll
    for (int it = 0; it < 16; it++) {
        int i = tid + it * 256;
        int r = i >> 5, c4 = (i & 31) << 2;
        uint32_t off = (uint32_t)(r * TROWB + c4 * 2);
        *(uint2*)(smem + OFF_WHI + off) = WH2[i];
        *(uint2*)(smem + OFF_WLO + off) = WL2[i];
    }
    __syncthreads();

    int warp_m = wid & 3;
    int warp_n = wid >> 2;       // == head
    int m0 = warp_m * 32;
    int n0 = warp_n * 64;

    float acc[2][8][4];
#pragma unroll
    for (int mt = 0; mt < 2; mt++)
#pragma unroll
        for (int nt = 0; nt < 8; nt++)
#pragma unroll
            for (int q = 0; q < 4; q++) acc[mt][nt][q] = 0.f;

    int a_row_in = (lane & 7) + ((lane >> 3) & 1) * 8;
    int a_koff = (lane >> 4) * 16;
    int b_row_in = (lane & 7) + ((lane >> 4) & 1) * 8;
    int b_koff = ((lane >> 3) & 1) * 16;

#pragma unroll
    for (int t = 0; t < 3; t++) {
        uint32_t abase = sb + ((t == 2) ? OFF_XLO : OFF_XHI);
        uint32_t bbase = sb + ((t == 1) ? OFF_WLO : OFF_WHI);
#pragma unroll
        for (int ks = 0; ks < 8; ks++) {
            int kb = ks * 32;
            uint32_t afr[2][4];
#pragma unroll
            for (int mt = 0; mt < 2; mt++) {
                uint32_t ad = abase + (uint32_t)((m0 + mt * 16 + a_row_in) * TROWB + kb + a_koff);
                ldsm4(ad, afr[mt][0], afr[mt][1], afr[mt][2], afr[mt][3]);
            }
            uint32_t bfr[4][4];
#pragma unroll
            for (int pt = 0; pt < 4; pt++) {
                uint32_t bd = bbase + (uint32_t)((n0 + pt * 16 + b_row_in) * TROWB + kb + b_koff);
                ldsm4(bd, bfr[pt][0], bfr[pt][1], bfr[pt][2], bfr[pt][3]);
            }
#pragma unroll
            for (int mt = 0; mt < 2; mt++)
#pragma unroll
                for (int nt = 0; nt < 8; nt++)
                    mma16816(acc[mt][nt], afr[mt], bfr[nt >> 1][(nt & 1) * 2],
                             bfr[nt >> 1][(nt & 1) * 2 + 1]);
        }
    }

    const float* sAS = (const float*)(smem + OFF_AS);
    const float* sAD = (const float*)(smem + OFF_AD);
    float ss[2][2] = {{0.f, 0.f}, {0.f, 0.f}};
    float dd[2][2] = {{0.f, 0.f}, {0.f, 0.f}};
#pragma unroll
    for (int nt = 0; nt < 8; nt++) {
        int col = n0 + nt * 8 + ((lane & 3) << 1);
        float as0 = sAS[col], as1 = sAS[col + 1];
        float ad0 = sAD[col], ad1 = sAD[col + 1];
#pragma unroll
        for (int mt = 0; mt < 2; mt++) {
            float c0 = acc[mt][nt][0], c1 = acc[mt][nt][1];
            float c2 = acc[mt][nt][2], c3 = acc[mt][nt][3];
            int r0 = row0 + m0 + mt * 16 + (lane >> 2);
            if (r0 < N) *(__half2*)(g_hh + (size_t)r0 * F + col) = __floats2half2_rn(c0, c1);
            if (r0 + 8 < N)
                *(__half2*)(g_hh + (size_t)(r0 + 8) * F + col) = __floats2half2_rn(c2, c3);
            ss[mt][0] += c0 * as0 + c1 * as1;
            ss[mt][1] += c2 * as0 + c3 * as1;
            dd[mt][0] += c0 * ad0 + c1 * ad1;
            dd[mt][1] += c2 * ad0 + c3 * ad1;
        }
    }
#pragma unroll
    for (int mt = 0; mt < 2; mt++)
#pragma unroll
        for (int rh = 0; rh < 2; rh++) {
            ss[mt][rh] += __shfl_xor_sync(0xffffffffu, ss[mt][rh], 1);
            ss[mt][rh] += __shfl_xor_sync(0xffffffffu, ss[mt][rh], 2);
            dd[mt][rh] += __shfl_xor_sync(0xffffffffu, dd[mt][rh], 1);
            dd[mt][rh] += __shfl_xor_sync(0xffffffffu, dd[mt][rh], 2);
        }
    if ((lane & 3) == 0) {
#pragma unroll
        for (int mt = 0; mt < 2; mt++)
#pragma unroll
            for (int rh = 0; rh < 2; rh++) {
                int m = row0 + m0 + mt * 16 + rh * 8 + (lane >> 2);
                if (m < N) {
                    g_als[m * NHEAD + warp_n] = ss[mt][rh];
                    g_ald[m * NHEAD + warp_n] = dd[mt][rh];
                }
            }
    }
}

// ---------------- fused CSR aggregation (fp16 gather, 8-edge ILP) ----------
// One warp per dst node; lane covers 4 feats (uint2), head = lane>>4.
// 8 edges batched: 8 esrc loads, then 8 independent als loads + 8 row gathers
// in flight before any consumption.
__global__ void k_aggregate(const float* __restrict__ bias, int residual, int fuse_lin,
                            const float* __restrict__ lin_w, const float* __restrict__ lin_b,
                            float* __restrict__ out, int N) {
    int d = (blockIdx.x * blockDim.x + threadIdx.x) >> 5;
    if (d >= N) return;
    int lane = threadIdx.x & 31;
    int head = lane >> 4;

    float ald = g_ald[d * NHEAD + head];
    int beg = g_rowptr[d], end = g_rowptr[d + 1];

    float4 acc = make_float4(0.f, 0.f, 0.f, 0.f);
    float sum = 0.f;
    const uint2* H2 = (const uint2*)g_hh;

    int j = beg;
    for (; j + 8 <= end; j += 8) {
        int s[8];
#pragma unroll
        for (int q = 0; q < 8; q++) s[q] = g_esrc[j + q];
        float al[8];
#pragma unroll
        for (int q = 0; q < 8; q++) al[q] = g_als[s[q] * NHEAD + head];
        uint2 r[8];
#pragma unroll
        for (int q = 0; q < 8; q++) r[q] = __ldg(H2 + (size_t)s[q] * 32 + lane);
#pragma unroll
        for (int q = 0; q < 8; q++) {
            float e = __expf(leaky(al[q] + ald));
            sum += e;
            float2 a = __half22float2(*(__half2*)&r[q].x);
            float2 b = __half22float2(*(__half2*)&r[q].y);
            acc.x += e * a.x; acc.y += e * a.y;
            acc.z += e * b.x; acc.w += e * b.y;
        }
    }
    for (; j < end; j++) {
        int s = g_esrc[j];
        float e = __expf(leaky(g_als[s * NHEAD + head] + ald));
        uint2 r = __ldg(H2 + (size_t)s * 32 + lane);
        float2 a = __half22float2(*(__half2*)&r.x);
        float2 b = __half22float2(*(__half2*)&r.y);
        sum += e;
        acc.x += e * a.x; acc.y += e * a.y;
        acc.z += e * b.x; acc.w += e * b.y;
    }

    float inv = 1.f / sum;
    float4 b4 = __ldg(((const float4*)bias) + lane);
    float4 v;
    v.x = acc.x * inv + b4.x; v.y = acc.y * inv + b4.y;
    v.z = acc.z * inv + b4.z; v.w = acc.w * inv + b4.w;
    if (residual) {
        float4 f = ((const float4*)g_feat)[(size_t)d * 32 + lane];
        v.x += f.x; v.y += f.y; v.z += f.z; v.w += f.w;
    }
    v.x = leaky(v.x); v.y = leaky(v.y); v.z = leaky(v.z); v.w = leaky(v.w);
    if (!fuse_lin) {
        ((float4*)g_feat)[(size_t)d * 32 + lane] = v;
    } else {
        float4 wv = __ldg(((const float4*)lin_w) + lane);
        float s = v.x * wv.x + v.y * wv.y + v.z * wv.z + v.w * wv.w;
#pragma unroll
        for (int o = 16; o; o >>= 1) s += __shfl_xor_sync(0xffffffffu, s, o);
        if (lane == 0) out[d] = s + __ldg(lin_b);
    }
}

// ---------------- host ----------------
extern "C" void kernel_launch(void* const* d_in, const int* in_sizes, int n_in,
                              void* d_out, int out_size) {
    const float* x = (const float*)d_in[0];
    const int* ei = (const int*)d_in[1];
    const float* W[3] = {(const float*)d_in[2], (const float*)d_in[6], (const float*)d_in[10]};
    const float* as[3] = {(const float*)d_in[3], (const float*)d_in[7], (const float*)d_in[11]};
    const float* ad[3] = {(const float*)d_in[4], (const float*)d_in[8], (const float*)d_in[12]};
    const float* bs[3] = {(const float*)d_in[5], (const float*)d_in[9], (const float*)d_in[13]};
    const float* lin_w = (const float*)d_in[14];
    const float* lin_b = (const float*)d_in[15];

    int N = in_sizes[0] / F;
    int E = in_sizes[1] / 2;
    int EE = E + N;
    int nb = (N + SCANB - 1) / SCANB;

    static bool init_done = false;
    static cudaStream_t s2;
    static cudaEvent_t ev_fork, ev_gemm1;
    if (!init_done) {
        cudaFuncSetAttribute(k_gemm_tc, cudaFuncAttributeMaxDynamicSharedMemorySize,
                             GEMM_SMEM_TOTAL);
        cudaStreamCreateWithFlags(&s2, cudaStreamNonBlocking);
        cudaEventCreateWithFlags(&ev_fork, cudaEventDisableTiming);
        cudaEventCreateWithFlags(&ev_gemm1, cudaEventDisableTiming);
        init_done = true;
    }

    float* feat_ptr = nullptr;
    cudaGetSymbolAddress((void**)&feat_ptr, g_feat);
    int* cnt_ptr = nullptr;
    cudaGetSymbolAddress((void**)&cnt_ptr, g_cnt);
    __nv_bfloat16* wth_ptr = nullptr;
    cudaGetSymbolAddress((void**)&wth_ptr, g_wth);
    __nv_bfloat16* wtl_ptr = nullptr;
    cudaGetSymbolAddress((void**)&wtl_ptr, g_wtl);

    const int TB = 256;
    int gemm_blocks = (N + TM - 1) / TM;
    int warpN_blocks = (N * 32 + TB - 1) / TB;
    int edge4_blocks = ((EE + 3) / 4 + TB - 1) / TB;
    int prep_blocks = (3 * F * F + TB - 1) / TB;

    // ---- fork: W prep + layer-1 GEMM on s2, CSR build on stream 0 ----
    cudaEventRecord(ev_fork, 0);
    cudaStreamWaitEvent(s2, ev_fork, 0);
    k_prep_w3<<<prep_blocks, TB, 0, s2>>>(W[0], W[1], W[2]);
    k_gemm_tc<<<gemm_blocks, 256, GEMM_SMEM_TOTAL, s2>>>(
        x, wth_ptr, wtl_ptr, as[0], ad[0], N);
    cudaEventRecord(ev_gemm1, s2);

    cudaMemsetAsync(cnt_ptr, 0, N * sizeof(int));
    k_build_hist<<<edge4_blocks, TB>>>(ei, E, N);
    k_scan1<<<nb, SCANB>>>(N);
    k_scan23<<<nb, SCANB>>>(N, EE, nb);
    k_fill<<<edge4_blocks, TB>>>(ei, E, N);

    // ---- join, then the rest on stream 0 ----
    cudaStreamWaitEvent(0, ev_gemm1, 0);
    k_aggregate<<<warpN_blocks, TB>>>(bs[0], 0, 0, lin_w, lin_b, (float*)d_out, N);

    for (int l = 1; l < 3; l++) {
        k_gemm_tc<<<gemm_blocks, 256, GEMM_SMEM_TOTAL>>>(
            feat_ptr, wth_ptr + (size_t)l * F * F, wtl_ptr + (size_t)l * F * F,
            as[l], ad[l], N);
        k_aggregate<<<warpN_blocks, TB>>>(bs[l], 1, l == 2, lin_w, lin_b,
                                          (float*)d_out, N);
    }
}